// round 2
// baseline (speedup 1.0000x reference)
#include <cuda_runtime.h>
#include <cstdint>

// Problem constants
#define NB 2
#define NL 256
#define NE 512
#define NH 8
#define ND 64   // head dim
// scale = 1/sqrt(64) = 0.125

// ---------------- device scratch (no allocations allowed) ----------------
__device__ float g_qp[NB*NL*NE];
__device__ float g_kp[NB*NL*NE];
__device__ float g_vp[NB*NL*NE];
__device__ float g_wk2[NB*NL*NH*NE];     // [b,k,h,g], pre-scaled by 1/8
__device__ float g_bias2[NB*NL*NH];      // pre-scaled by 1/8
__device__ float g_S1[NB*NH*NL*NL];      // [b,h,q,k], pre-scaled by 1/8
__device__ float g_S[NB*NL*NL*NH];       // logits, [b,q,k,h]
__device__ float g_P[NB*NH*NL*NL];       // probs, [b,h,q,k]
__device__ float g_attn[NB*NL*NE];       // [b,q, h*64+e]

// ---------------- generic 64x64 tiled fp32 GEMM ----------------
// C[m,n] = alpha * sum_k A[m,k]*B[k,n]   (TRANS_B: B[n,k])  (+ bias[n])
// Requires: M,N multiples of 64 (per grid), K multiple of 16, lda/ldb mult of 4.
#define BM 64
#define BN 64
#define BK 16

template<bool TRANS_B>
__device__ __forceinline__ void gemm_tile(
    const float* __restrict__ A, int lda,
    const float* __restrict__ Bmat, int ldb,
    float* __restrict__ C, int ldc,
    int K, float alpha, const float* __restrict__ bias)
{
    __shared__ float As[BK][BM + 4];
    __shared__ float Bs[BK][BN + 4];

    const int tid = threadIdx.x;        // 256 threads
    const int tx = tid & 15;            // n direction
    const int ty = tid >> 4;            // m direction
    const int bm = blockIdx.y * BM;
    const int bn = blockIdx.x * BN;

    float acc[4][4];
#pragma unroll
    for (int i = 0; i < 4; i++)
#pragma unroll
        for (int j = 0; j < 4; j++) acc[i][j] = 0.f;

    for (int k0 = 0; k0 < K; k0 += BK) {
        // A tile: 64 rows x 16 cols -> As[k][m] (transposed)
        {
            int r = tid >> 2;
            int c4 = (tid & 3) * 4;
            float4 av = *reinterpret_cast<const float4*>(
                A + (size_t)(bm + r) * lda + k0 + c4);
            As[c4 + 0][r] = av.x; As[c4 + 1][r] = av.y;
            As[c4 + 2][r] = av.z; As[c4 + 3][r] = av.w;
        }
        if (!TRANS_B) {
            // B tile: 16 rows(k) x 64 cols(n)
            int r = tid >> 4;
            int c = (tid & 15) * 4;
            float4 bv = *reinterpret_cast<const float4*>(
                Bmat + (size_t)(k0 + r) * ldb + bn + c);
            Bs[r][c + 0] = bv.x; Bs[r][c + 1] = bv.y;
            Bs[r][c + 2] = bv.z; Bs[r][c + 3] = bv.w;
        } else {
            // B stored [n,k]: load 64 rows(n) x 16 cols(k) -> Bs[k][n]
            int r = tid >> 2;
            int c4 = (tid & 3) * 4;
            float4 bv = *reinterpret_cast<const float4*>(
                Bmat + (size_t)(bn + r) * ldb + k0 + c4);
            Bs[c4 + 0][r] = bv.x; Bs[c4 + 1][r] = bv.y;
            Bs[c4 + 2][r] = bv.z; Bs[c4 + 3][r] = bv.w;
        }
        __syncthreads();

#pragma unroll
        for (int kk = 0; kk < BK; kk++) {
            float ar[4], brg[4];
#pragma unroll
            for (int i = 0; i < 4; i++) ar[i] = As[kk][ty * 4 + i];
#pragma unroll
            for (int j = 0; j < 4; j++) brg[j] = Bs[kk][tx * 4 + j];
#pragma unroll
            for (int i = 0; i < 4; i++)
#pragma unroll
                for (int j = 0; j < 4; j++)
                    acc[i][j] += ar[i] * brg[j];
        }
        __syncthreads();
    }

#pragma unroll
    for (int i = 0; i < 4; i++) {
        int row = bm + ty * 4 + i;
#pragma unroll
        for (int j = 0; j < 4; j++) {
            int col = bn + tx * 4 + j;
            float v = acc[i][j] * alpha;
            if (bias) v += bias[col];
            C[(size_t)row * ldc + col] = v;
        }
    }
}

// ---------------- K1: projections qp = query@Wq, kp = key@Wk, vp = value@Wq ----------------
__global__ void k_proj(const float* __restrict__ q, const float* __restrict__ k,
                       const float* __restrict__ v,
                       const float* __restrict__ Wq, const float* __restrict__ Wk)
{
    int z = blockIdx.z;
    const float* A = (z == 0) ? q : (z == 1) ? k : v;
    const float* W = (z == 1) ? Wk : Wq;   // value uses Wq (bug preserved from source)
    float* C = (z == 0) ? g_qp : (z == 1) ? g_kp : g_vp;
    gemm_tile<false>(A, NE, W, NE, C, NE, NE, 1.0f, nullptr);
}

// ---------------- K2: Wk2[b,k,h,:] = (1/8) * kp_head(b,k,h,:) @ Wr[h*64:(h+1)*64, :] ----------------
__global__ void k_wk2(const float* __restrict__ Wr)
{
    int h = blockIdx.z;
    const float* A = g_kp + h * ND;                     // (NB*NL) x ND, lda=NE
    const float* Bw = Wr + (size_t)h * ND * NE;         // ND x NE
    float* C = g_wk2 + (size_t)h * NE;                  // row stride NH*NE
    gemm_tile<false>(A, NE, Bw, NE, C, NH * NE, ND, 0.125f, nullptr);
}

// ---------------- K2b: bias2[b,k,h] = (1/8) * dot(br_head, kp_head) ----------------
__global__ void k_bias2(const float* __restrict__ br)
{
    int idx = blockIdx.x * blockDim.x + threadIdx.x;  // NB*NL*NH = 4096
    if (idx >= NB * NL * NH) return;
    int h = idx & (NH - 1);
    int row = idx >> 3;
    float s = 0.f;
#pragma unroll 8
    for (int e = 0; e < ND; e++)
        s += br[h * ND + e] * g_kp[(size_t)row * NE + h * ND + e];
    g_bias2[idx] = s * 0.125f;
}

// ---------------- K3: S1[b,h,q,k] = (1/8) * qp_h @ kp_h^T ----------------
__global__ void k_s1()
{
    int z = blockIdx.z;            // b*NH + h
    int b = z >> 3, h = z & 7;
    const float* A = g_qp + (size_t)b * NL * NE + h * ND;
    const float* Bw = g_kp + (size_t)b * NL * NE + h * ND;
    float* C = g_S1 + (size_t)z * NL * NL;
    gemm_tile<true>(A, NE, Bw, NE, C, NL, ND, 0.125f, nullptr);
}

// ---------------- K4: relation streaming pass ----------------
// Block = (kpos, b). Loads Wk2[b,k] (8x512 = 16KB) to smem; each warp handles
// 4 q rows per pass; logit = relation.Wk2 + S1 + bias2 -> g_S[b,q,k,h].
__global__ void __launch_bounds__(256, 2) k_rel(const float* __restrict__ relation)
{
    const int kpos = blockIdx.x;
    const int b = blockIdx.y;
    const int tid = threadIdx.x;
    const int warp = tid >> 5;
    const int lane = tid & 31;

    __shared__ float4 wk2s4[NH * NE / 4];   // 16 KB
    __shared__ float b2s[NH];

    {
        const float4* src = reinterpret_cast<const float4*>(
            g_wk2 + (size_t)(b * NL + kpos) * NH * NE);
        for (int i = tid; i < NH * NE / 4; i += 256) wk2s4[i] = src[i];
        if (tid < NH) b2s[tid] = g_bias2[(size_t)(b * NL + kpos) * NH + tid];
    }
    __syncthreads();

    for (int pass = 0; pass < 8; pass++) {
        const int q0 = pass * 32 + warp * 4;   // this warp: q0..q0+3

        const float4* rp0 = reinterpret_cast<const float4*>(
            relation + ((size_t)(b * NL + q0 + 0) * NL + kpos) * NE);
        const float4* rp1 = reinterpret_cast<const float4*>(
            relation + ((size_t)(b * NL + q0 + 1) * NL + kpos) * NE);
        const float4* rp2 = reinterpret_cast<const float4*>(
            relation + ((size_t)(b * NL + q0 + 2) * NL + kpos) * NE);
        const float4* rp3 = reinterpret_cast<const float4*>(
            relation + ((size_t)(b * NL + q0 + 3) * NL + kpos) * NE);

        float vals[32];   // vals[qq*8 + h]
#pragma unroll
        for (int i = 0; i < 32; i++) vals[i] = 0.f;

#pragma unroll
        for (int i128 = 0; i128 < 4; i128++) {
            float4 r0 = rp0[i128 * 32 + lane];
            float4 r1 = rp1[i128 * 32 + lane];
            float4 r2 = rp2[i128 * 32 + lane];
            float4 r3 = rp3[i128 * 32 + lane];
#pragma unroll
            for (int h = 0; h < NH; h++) {
                float4 w = wk2s4[h * 128 + i128 * 32 + lane];
                vals[0 * 8 + h] += r0.x * w.x + r0.y * w.y + r0.z * w.z + r0.w * w.w;
                vals[1 * 8 + h] += r1.x * w.x + r1.y * w.y + r1.z * w.z + r1.w * w.w;
                vals[2 * 8 + h] += r2.x * w.x + r2.y * w.y + r2.z * w.z + r2.w * w.w;
                vals[3 * 8 + h] += r3.x * w.x + r3.y * w.y + r3.z * w.z + r3.w * w.w;
            }
        }

        // transpose-reduce: lane l ends with full sum of vals[l]
#pragma unroll
        for (int off = 16; off > 0; off >>= 1) {
            bool hi = (lane & off) != 0;
#pragma unroll
            for (int i = 0; i < 16; i++) {
                if (i < off) {
                    float send = hi ? vals[i] : vals[i + off];
                    float recv = __shfl_xor_sync(0xffffffffu, send, off);
                    vals[i] = (hi ? vals[i + off] : vals[i]) + recv;
                }
            }
        }

        const int qq = lane >> 3;
        const int h = lane & 7;
        const int q = q0 + qq;
        float s1 = g_S1[(((size_t)b * NH + h) * NL + q) * NL + kpos];
        g_S[(((size_t)b * NL + q) * NL + kpos) * NH + h] = vals[0] + s1 + b2s[h];
    }
}

// ---------------- K5: softmax over k + write probs ----------------
__global__ void k_softmax(float* __restrict__ a_out, int write_a)
{
    const int q = blockIdx.x;
    const int b = blockIdx.y;
    const int tid = threadIdx.x;
    const int warp = tid >> 5;   // = head
    const int lane = tid & 31;

    __shared__ float Ss[NL][NH + 1];   // padded

    // coalesced load of S[b,q,:,:] (2048 floats)
    const float* Srow = g_S + (size_t)(b * NL + q) * NL * NH;
    for (int i = tid; i < NL * NH / 4; i += 256) {
        float4 v = reinterpret_cast<const float4*>(Srow)[i];
        int idx = i * 4;
        int kk = idx >> 3, h0 = idx & 7;
        Ss[kk][h0] = v.x; Ss[kk][h0 + 1] = v.y;
        Ss[kk][h0 + 2] = v.z; Ss[kk][h0 + 3] = v.w;
    }
    __syncthreads();

    const int h = warp;
    float x[8];
#pragma unroll
    for (int i = 0; i < 8; i++) x[i] = Ss[lane + 32 * i][h];

    float m = x[0];
#pragma unroll
    for (int i = 1; i < 8; i++) m = fmaxf(m, x[i]);
#pragma unroll
    for (int off = 16; off > 0; off >>= 1)
        m = fmaxf(m, __shfl_xor_sync(0xffffffffu, m, off));

    float e[8], s = 0.f;
#pragma unroll
    for (int i = 0; i < 8; i++) { e[i] = __expf(x[i] - m); s += e[i]; }
#pragma unroll
    for (int off = 16; off > 0; off >>= 1)
        s += __shfl_xor_sync(0xffffffffu, s, off);
    float inv = 1.0f / s;

    // probs to contiguous g_P[b,h,q,:]
    float* Prow = g_P + (((size_t)b * NH + h) * NL + q) * NL;
#pragma unroll
    for (int i = 0; i < 8; i++) {
        float p = e[i] * inv;
        Prow[lane + 32 * i] = p;
        Ss[lane + 32 * i][h] = p;    // own column only, no cross-warp hazard
    }
    __syncthreads();

    if (write_a) {
        float* arow = a_out + (size_t)(b * NL + q) * NL * NH;
        int t = tid;   // 256 threads, one k each
        float4 v0 = make_float4(Ss[t][0], Ss[t][1], Ss[t][2], Ss[t][3]);
        float4 v1 = make_float4(Ss[t][4], Ss[t][5], Ss[t][6], Ss[t][7]);
        reinterpret_cast<float4*>(arow + t * 8)[0] = v0;
        reinterpret_cast<float4*>(arow + t * 8)[1] = v1;
    }
}

// ---------------- K6: attn = P @ vp per (b,h) ----------------
__global__ void k_attn()
{
    int z = blockIdx.z;           // b*NH + h
    int b = z >> 3, h = z & 7;
    const float* A = g_P + (size_t)z * NL * NL;              // L x L
    const float* Bw = g_vp + (size_t)b * NL * NE + h * ND;   // L x 64, ldb=NE
    float* C = g_attn + (size_t)b * NL * NE + h * ND;        // ldc=NE
    gemm_tile<false>(A, NL, Bw, NE, C, NE, NL, 1.0f, nullptr);
}

// ---------------- K7: out = attn @ Wo^T + bo ----------------
__global__ void k_out(const float* __restrict__ Wo, const float* __restrict__ bo,
                      float* __restrict__ out)
{
    gemm_tile<true>(g_attn, NE, Wo, NE, out, NE, NE, 1.0f, bo);
}

// ---------------- launch ----------------
extern "C" void kernel_launch(void* const* d_in, const int* in_sizes, int n_in,
                              void* d_out, int out_size)
{
    const float* query    = (const float*)d_in[0];
    const float* key      = (const float*)d_in[1];
    const float* value    = (const float*)d_in[2];
    const float* relation = (const float*)d_in[3];
    const float* Wq       = (const float*)d_in[4];
    const float* Wk       = (const float*)d_in[5];
    // d_in[6] = Wv — unused (source bug: value projected with Wq)
    const float* Wr       = (const float*)d_in[7];
    const float* br       = (const float*)d_in[8];
    const float* Wo       = (const float*)d_in[9];
    const float* bo       = (const float*)d_in[10];

    float* out = (float*)d_out;
    const int out_elems = NB * NL * NE;            // 262144
    const int a_elems   = NB * NL * NL * NH;       // 1048576
    int write_a = (out_size >= out_elems + a_elems) ? 1 : 0;
    float* a_out = out + out_elems;

    dim3 blk(256);
    k_proj   <<<dim3(8, 8, 3),  blk>>>(query, key, value, Wq, Wk);
    k_wk2    <<<dim3(8, 8, 8),  blk>>>(Wr);
    k_bias2  <<<16, 256>>>(br);
    k_s1     <<<dim3(4, 4, 16), blk>>>();
    k_rel    <<<dim3(NL, NB),   blk>>>(relation);
    k_softmax<<<dim3(NL, NB),   blk>>>(a_out, write_a);
    k_attn   <<<dim3(1, 4, 16), blk>>>();
    k_out    <<<dim3(8, 8, 1),  blk>>>(Wo, bo, out);
}

// round 3
// speedup vs baseline: 1.0871x; 1.0871x over previous
#include <cuda_runtime.h>
#include <cstdint>

// Problem constants
#define NB 2
#define NL 256
#define NE 512
#define NH 8
#define ND 64   // head dim
// scale = 1/sqrt(64) = 0.125

// ---------------- device scratch (no allocations allowed) ----------------
__device__ float g_qp[NB*NL*NE];
__device__ float g_kp[NB*NL*NE];
__device__ float g_vp[NB*NL*NE];
__device__ float g_wk2[NB*NL*NH*NE];     // [b,k,h,g], pre-scaled by 1/8
__device__ float g_bias2[NB*NL*NH];      // pre-scaled by 1/8
__device__ float g_S1[NB*NH*NL*NL];      // [b,h,q,k], pre-scaled by 1/8
__device__ float g_S[NB*NL*NL*NH];       // logits, [b,q,k,h]
__device__ float g_P[NB*NH*NL*NL];       // probs, [b,h,q,k]
__device__ float g_attn[NB*NL*NE];       // [b,q, h*64+e]

// ---------------- GEMM v2: double-buffered tiled fp32 GEMM ----------------
// C[m,n] = alpha * sum_k A[m,k]*B[k,n]   (TRANS_B: B stored [n,k])  (+bias[n])
// BN = 64 fixed, BK = 16 fixed, 256 threads. BM = 64 (4x4 microtile) or 32 (2x4).
// Requires K % 16 == 0, leading dims multiples of 4.
#define BK 16
#define BN 64

template<int BM, bool TRANS_B>
__device__ __forceinline__ void gemm2(
    const float* __restrict__ A, int lda,
    const float* __restrict__ Bmat, int ldb,
    float* __restrict__ C, int ldc,
    int K, float alpha, const float* __restrict__ bias)
{
    constexpr int TM = BM / 16;   // 4 or 2
    __shared__ float As[2][BK][BM + 4];
    __shared__ float Bs[2][BK][BN + 4];

    const int tid = threadIdx.x;        // 256 threads
    const int tx = tid & 15;            // n direction
    const int ty = tid >> 4;            // m direction
    const int bm = blockIdx.y * BM;
    const int bn = blockIdx.x * BN;

    // load-index precompute
    const int aRow = tid >> 2;              // for BM=64: 0..63; BM=32: guard tid<128
    const int aC4  = (tid & 3) * 4;
    const int bRowN = tid >> 4;             // !TRANS: k row 0..15
    const int bColN = (tid & 15) * 4;
    const int bRowT = tid >> 2;             // TRANS: n row 0..63
    const int bC4T  = (tid & 3) * 4;

    float4 a_reg = make_float4(0.f,0.f,0.f,0.f), b_reg;

    const bool aAct = (BM == 64) || (tid < BM * 4);

    auto ldg_tiles = [&](int k0) {
        if (aAct)
            a_reg = *reinterpret_cast<const float4*>(
                A + (size_t)(bm + aRow) * lda + k0 + aC4);
        if (!TRANS_B)
            b_reg = *reinterpret_cast<const float4*>(
                Bmat + (size_t)(k0 + bRowN) * ldb + bn + bColN);
        else
            b_reg = *reinterpret_cast<const float4*>(
                Bmat + (size_t)(bn + bRowT) * ldb + k0 + bC4T);
    };
    auto sts_tiles = [&](int p) {
        if (aAct) {
            As[p][aC4 + 0][aRow] = a_reg.x; As[p][aC4 + 1][aRow] = a_reg.y;
            As[p][aC4 + 2][aRow] = a_reg.z; As[p][aC4 + 3][aRow] = a_reg.w;
        }
        if (!TRANS_B) {
            Bs[p][bRowN][bColN + 0] = b_reg.x; Bs[p][bRowN][bColN + 1] = b_reg.y;
            Bs[p][bRowN][bColN + 2] = b_reg.z; Bs[p][bRowN][bColN + 3] = b_reg.w;
        } else {
            Bs[p][bC4T + 0][bRowT] = b_reg.x; Bs[p][bC4T + 1][bRowT] = b_reg.y;
            Bs[p][bC4T + 2][bRowT] = b_reg.z; Bs[p][bC4T + 3][bRowT] = b_reg.w;
        }
    };

    float acc[TM][4];
#pragma unroll
    for (int i = 0; i < TM; i++)
#pragma unroll
        for (int j = 0; j < 4; j++) acc[i][j] = 0.f;

    const int niter = K / BK;
    ldg_tiles(0);
    sts_tiles(0);
    __syncthreads();

    int p = 0;
    for (int it = 0; it < niter; ++it) {
        if (it + 1 < niter) ldg_tiles((it + 1) * BK);   // in flight during compute

#pragma unroll
        for (int kk = 0; kk < BK; kk++) {
            float ar[TM];
            if (TM == 4) {
                float4 av = *reinterpret_cast<const float4*>(&As[p][kk][ty * 4]);
                ar[0] = av.x; ar[1] = av.y; ar[2] = av.z; ar[3] = av.w;
            } else {
                float2 av = *reinterpret_cast<const float2*>(&As[p][kk][ty * 2]);
                ar[0] = av.x; ar[1] = av.y;
            }
            float4 bv = *reinterpret_cast<const float4*>(&Bs[p][kk][tx * 4]);
#pragma unroll
            for (int i = 0; i < TM; i++) {
                acc[i][0] += ar[i] * bv.x;
                acc[i][1] += ar[i] * bv.y;
                acc[i][2] += ar[i] * bv.z;
                acc[i][3] += ar[i] * bv.w;
            }
        }

        if (it + 1 < niter) {
            sts_tiles(p ^ 1);
            __syncthreads();
            p ^= 1;
        }
    }

#pragma unroll
    for (int i = 0; i < TM; i++) {
        int row = bm + ty * TM + i;
        int col = bn + tx * 4;
        float4 v;
        v.x = acc[i][0] * alpha; v.y = acc[i][1] * alpha;
        v.z = acc[i][2] * alpha; v.w = acc[i][3] * alpha;
        if (bias) {
            v.x += bias[col + 0]; v.y += bias[col + 1];
            v.z += bias[col + 2]; v.w += bias[col + 3];
        }
        *reinterpret_cast<float4*>(C + (size_t)row * ldc + col) = v;
    }
}

// ---------------- K1: projections qp = query@Wq, kp = key@Wk, vp = value@Wq ----------------
__global__ void __launch_bounds__(256) k_proj(
    const float* __restrict__ q, const float* __restrict__ k,
    const float* __restrict__ v,
    const float* __restrict__ Wq, const float* __restrict__ Wk)
{
    int z = blockIdx.z;
    const float* A = (z == 0) ? q : (z == 1) ? k : v;
    const float* W = (z == 1) ? Wk : Wq;   // value uses Wq (bug preserved from source)
    float* C = (z == 0) ? g_qp : (z == 1) ? g_kp : g_vp;
    gemm2<64, false>(A, NE, W, NE, C, NE, NE, 1.0f, nullptr);
}

// ---------------- K2 (merged): wk2 (z<8), S1 (z in 8..23), bias2 (z==24) ----------------
__global__ void __launch_bounds__(256) k_mid(
    const float* __restrict__ Wr, const float* __restrict__ br)
{
    const int z = blockIdx.z;
    if (z < 8) {
        // Wk2[b,k,h,:] = (1/8) * kp_head(b,k,h,:) @ Wr[h*64:(h+1)*64, :]
        const int h = z;
        gemm2<64, false>(g_kp + h * ND, NE,
                         Wr + (size_t)h * ND * NE, NE,
                         g_wk2 + (size_t)h * NE, NH * NE,
                         ND, 0.125f, nullptr);
    } else if (z < 24) {
        // S1[b,h,q,k] = (1/8) * qp_h @ kp_h^T
        if (blockIdx.x >= 4 || blockIdx.y >= 4) return;
        const int zz = z - 8;            // b*NH + h
        const int b = zz >> 3, h = zz & 7;
        gemm2<64, true>(g_qp + (size_t)b * NL * NE + h * ND, NE,
                        g_kp + (size_t)b * NL * NE + h * ND, NE,
                        g_S1 + (size_t)zz * NL * NL, NL,
                        ND, 0.125f, nullptr);
    } else {
        // bias2[b,k,h] = (1/8) * dot(br_head, kp_head)
        const int blk = blockIdx.y * 8 + blockIdx.x;
        if (blk >= 16) return;
        const int idx = blk * 256 + threadIdx.x;   // NB*NL*NH = 4096
        const int h = idx & (NH - 1);
        const int row = idx >> 3;
        float s = 0.f;
#pragma unroll 8
        for (int e = 0; e < ND; e++)
            s += br[h * ND + e] * g_kp[(size_t)row * NE + h * ND + e];
        g_bias2[idx] = s * 0.125f;
    }
}

// ---------------- K4: relation streaming pass ----------------
__global__ void __launch_bounds__(256, 2) k_rel(const float* __restrict__ relation)
{
    const int kpos = blockIdx.x;
    const int b = blockIdx.y;
    const int tid = threadIdx.x;
    const int warp = tid >> 5;
    const int lane = tid & 31;

    __shared__ float4 wk2s4[NH * NE / 4];   // 16 KB
    __shared__ float b2s[NH];

    {
        const float4* src = reinterpret_cast<const float4*>(
            g_wk2 + (size_t)(b * NL + kpos) * NH * NE);
        for (int i = tid; i < NH * NE / 4; i += 256) wk2s4[i] = src[i];
        if (tid < NH) b2s[tid] = g_bias2[(size_t)(b * NL + kpos) * NH + tid];
    }
    __syncthreads();

    for (int pass = 0; pass < 8; pass++) {
        const int q0 = pass * 32 + warp * 4;   // this warp: q0..q0+3

        const float4* rp0 = reinterpret_cast<const float4*>(
            relation + ((size_t)(b * NL + q0 + 0) * NL + kpos) * NE);
        const float4* rp1 = reinterpret_cast<const float4*>(
            relation + ((size_t)(b * NL + q0 + 1) * NL + kpos) * NE);
        const float4* rp2 = reinterpret_cast<const float4*>(
            relation + ((size_t)(b * NL + q0 + 2) * NL + kpos) * NE);
        const float4* rp3 = reinterpret_cast<const float4*>(
            relation + ((size_t)(b * NL + q0 + 3) * NL + kpos) * NE);

        float vals[32];   // vals[qq*8 + h]
#pragma unroll
        for (int i = 0; i < 32; i++) vals[i] = 0.f;

#pragma unroll
        for (int i128 = 0; i128 < 4; i128++) {
            float4 r0 = rp0[i128 * 32 + lane];
            float4 r1 = rp1[i128 * 32 + lane];
            float4 r2 = rp2[i128 * 32 + lane];
            float4 r3 = rp3[i128 * 32 + lane];
#pragma unroll
            for (int h = 0; h < NH; h++) {
                float4 w = wk2s4[h * 128 + i128 * 32 + lane];
                vals[0 * 8 + h] += r0.x * w.x + r0.y * w.y + r0.z * w.z + r0.w * w.w;
                vals[1 * 8 + h] += r1.x * w.x + r1.y * w.y + r1.z * w.z + r1.w * w.w;
                vals[2 * 8 + h] += r2.x * w.x + r2.y * w.y + r2.z * w.z + r2.w * w.w;
                vals[3 * 8 + h] += r3.x * w.x + r3.y * w.y + r3.z * w.z + r3.w * w.w;
            }
        }

        // transpose-reduce: lane l ends with full sum of vals[l]
#pragma unroll
        for (int off = 16; off > 0; off >>= 1) {
            bool hi = (lane & off) != 0;
#pragma unroll
            for (int i = 0; i < 16; i++) {
                if (i < off) {
                    float send = hi ? vals[i] : vals[i + off];
                    float recv = __shfl_xor_sync(0xffffffffu, send, off);
                    vals[i] = (hi ? vals[i + off] : vals[i]) + recv;
                }
            }
        }

        const int qq = lane >> 3;
        const int h = lane & 7;
        const int q = q0 + qq;
        float s1 = g_S1[(((size_t)b * NH + h) * NL + q) * NL + kpos];
        g_S[(((size_t)b * NL + q) * NL + kpos) * NH + h] = vals[0] + s1 + b2s[h];
    }
}

// ---------------- K5: softmax over k + write probs ----------------
__global__ void __launch_bounds__(256) k_softmax(float* __restrict__ a_out, int write_a)
{
    const int q = blockIdx.x;
    const int b = blockIdx.y;
    const int tid = threadIdx.x;
    const int warp = tid >> 5;   // = head
    const int lane = tid & 31;

    __shared__ float Ss[NL][NH + 1];   // padded

    const float* Srow = g_S + (size_t)(b * NL + q) * NL * NH;
    for (int i = tid; i < NL * NH / 4; i += 256) {
        float4 v = reinterpret_cast<const float4*>(Srow)[i];
        int idx = i * 4;
        int kk = idx >> 3, h0 = idx & 7;
        Ss[kk][h0] = v.x; Ss[kk][h0 + 1] = v.y;
        Ss[kk][h0 + 2] = v.z; Ss[kk][h0 + 3] = v.w;
    }
    __syncthreads();

    const int h = warp;
    float x[8];
#pragma unroll
    for (int i = 0; i < 8; i++) x[i] = Ss[lane + 32 * i][h];

    float m = x[0];
#pragma unroll
    for (int i = 1; i < 8; i++) m = fmaxf(m, x[i]);
#pragma unroll
    for (int off = 16; off > 0; off >>= 1)
        m = fmaxf(m, __shfl_xor_sync(0xffffffffu, m, off));

    float e[8], s = 0.f;
#pragma unroll
    for (int i = 0; i < 8; i++) { e[i] = __expf(x[i] - m); s += e[i]; }
#pragma unroll
    for (int off = 16; off > 0; off >>= 1)
        s += __shfl_xor_sync(0xffffffffu, s, off);
    float inv = 1.0f / s;

    float* Prow = g_P + (((size_t)b * NH + h) * NL + q) * NL;
#pragma unroll
    for (int i = 0; i < 8; i++) {
        float p = e[i] * inv;
        Prow[lane + 32 * i] = p;
        Ss[lane + 32 * i][h] = p;
    }
    __syncthreads();

    if (write_a) {
        float* arow = a_out + (size_t)(b * NL + q) * NL * NH;
        int t = tid;
        float4 v0 = make_float4(Ss[t][0], Ss[t][1], Ss[t][2], Ss[t][3]);
        float4 v1 = make_float4(Ss[t][4], Ss[t][5], Ss[t][6], Ss[t][7]);
        reinterpret_cast<float4*>(arow + t * 8)[0] = v0;
        reinterpret_cast<float4*>(arow + t * 8)[1] = v1;
    }
}

// ---------------- K6: attn = P @ vp per (b,h)  (32x64 tiles -> 128 blocks) ----------------
__global__ void __launch_bounds__(256) k_attn()
{
    int z = blockIdx.z;           // b*NH + h
    int b = z >> 3, h = z & 7;
    const float* A = g_P + (size_t)z * NL * NL;              // L x L
    const float* Bw = g_vp + (size_t)b * NL * NE + h * ND;   // L x 64, ldb=NE
    float* C = g_attn + (size_t)b * NL * NE + h * ND;        // ldc=NE
    gemm2<32, false>(A, NL, Bw, NE, C, NE, NL, 1.0f, nullptr);
}

// ---------------- K7: out = attn @ Wo^T + bo  (32x64 tiles -> 128 blocks) ----------------
__global__ void __launch_bounds__(256) k_out(
    const float* __restrict__ Wo, const float* __restrict__ bo,
    float* __restrict__ out)
{
    gemm2<32, true>(g_attn, NE, Wo, NE, out, NE, NE, 1.0f, bo);
}

// ---------------- launch ----------------
extern "C" void kernel_launch(void* const* d_in, const int* in_sizes, int n_in,
                              void* d_out, int out_size)
{
    const float* query    = (const float*)d_in[0];
    const float* key      = (const float*)d_in[1];
    const float* value    = (const float*)d_in[2];
    const float* relation = (const float*)d_in[3];
    const float* Wq       = (const float*)d_in[4];
    const float* Wk       = (const float*)d_in[5];
    // d_in[6] = Wv — unused (source bug: value projected with Wq)
    const float* Wr       = (const float*)d_in[7];
    const float* br       = (const float*)d_in[8];
    const float* Wo       = (const float*)d_in[9];
    const float* bo       = (const float*)d_in[10];

    float* out = (float*)d_out;
    const int out_elems = NB * NL * NE;            // 262144
    const int a_elems   = NB * NL * NL * NH;       // 1048576
    int write_a = (out_size >= out_elems + a_elems) ? 1 : 0;
    float* a_out = out + out_elems;

    dim3 blk(256);
    k_proj   <<<dim3(8, 8, 3),   blk>>>(query, key, value, Wq, Wk);
    k_mid    <<<dim3(8, 8, 25),  blk>>>(Wr, br);
    k_rel    <<<dim3(NL, NB),    blk>>>(relation);
    k_softmax<<<dim3(NL, NB),    blk>>>(a_out, write_a);
    k_attn   <<<dim3(1, 8, 16),  blk>>>();
    k_out    <<<dim3(8, 16, 1),  blk>>>(Wo, bo, out);
}

// round 6
// speedup vs baseline: 1.1362x; 1.0451x over previous
#include <cuda_runtime.h>
#include <cstdint>

// Problem constants
#define NB 2
#define NL 256
#define NE 512
#define NH 8
#define ND 64   // head dim
// scale = 1/sqrt(64) = 0.125

// ---------------- device scratch (no allocations allowed) ----------------
__device__ float g_qp[NB*NL*NE];
__device__ float g_kp[NB*NL*NE];
__device__ float g_vp[NB*NL*NE];
__device__ float g_wk2[NB*NL*NH*NE];     // [b,k,h,g], pre-scaled by 1/8
__device__ float g_bias2[NB*NL*NH];      // pre-scaled by 1/8
__device__ float g_S1[NB*NH*NL*NL];      // [b,h,q,k], pre-scaled by 1/8
__device__ float g_S[NB*NL*NL*NH];       // logits, [b,q,k,h]
__device__ float g_P[NB*NH*NL*NL];       // probs, [b,h,q,k]
__device__ float g_attn[NB*NL*NE];       // [b,q, h*64+e]

// ---------------- packed f32x2 helpers ----------------
__device__ __forceinline__ unsigned long long f2pack(float lo, float hi) {
    unsigned long long r;
    asm("mov.b64 %0, {%1, %2};" : "=l"(r) : "f"(lo), "f"(hi));
    return r;
}
__device__ __forceinline__ void f2unpack(float& lo, float& hi, unsigned long long v) {
    asm("mov.b64 {%0, %1}, %2;" : "=f"(lo), "=f"(hi) : "l"(v));
}
__device__ __forceinline__ void fma2(unsigned long long& d,
                                     unsigned long long a, unsigned long long b) {
    asm("fma.rn.f32x2 %0, %1, %2, %0;" : "+l"(d) : "l"(a), "l"(b));
}

// ---------------- GEMM v3: pipelined fp32x2 GEMM ----------------
// C[m,n] = alpha * sum_k A[m,k]*B[k,n]   (TRANS_B: B stored [n,k])  (+bias[n])
// BN = 64, BK = 16, 256 threads. BM = 128 (8x4 microtile, 2 m-quadrants)
// or BM = 64 (4x4 microtile). Accumulation via fma.rn.f32x2 over m-pairs.
// Requires K % 16 == 0, dims multiples of tile, leading dims multiples of 4.
template<int BM, bool TRANS_B>
__device__ __forceinline__ void gemm3(
    const float* __restrict__ A, int lda,
    const float* __restrict__ Bmat, int ldb,
    float* __restrict__ C, int ldc,
    int K, float alpha, const float* __restrict__ bias)
{
    constexpr int QM = BM / 64;           // m-quadrants: 1 or 2
    constexpr int NP = 2 * QM;            // acc row-pairs per thread
    __shared__ float As[2][16][BM + 4];
    __shared__ float Bs[2][16][64 + 4];

    const int tid = threadIdx.x;          // 256 threads
    const int tx = tid & 15;              // n direction
    const int ty = tid >> 4;              // m direction
    const int bm = blockIdx.y * BM;
    const int bn = blockIdx.x * 64;

    const int aRow = tid >> 2;            // 0..63
    const int aC4  = (tid & 3) * 4;
    const int bRowN = tid >> 4;           // 0..15 (k row, !TRANS)
    const int bColN = (tid & 15) * 4;

    float4 a_reg[QM];
    float4 b_reg;

    auto ldg = [&](int k0) {
#pragma unroll
        for (int q = 0; q < QM; q++)
            a_reg[q] = *reinterpret_cast<const float4*>(
                A + (size_t)(bm + aRow + q * 64) * lda + k0 + aC4);
        if (!TRANS_B)
            b_reg = *reinterpret_cast<const float4*>(
                Bmat + (size_t)(k0 + bRowN) * ldb + bn + bColN);
        else
            b_reg = *reinterpret_cast<const float4*>(
                Bmat + (size_t)(bn + aRow) * ldb + k0 + aC4);
    };
    auto sts = [&](int p) {
#pragma unroll
        for (int q = 0; q < QM; q++) {
            As[p][aC4 + 0][aRow + q * 64] = a_reg[q].x;
            As[p][aC4 + 1][aRow + q * 64] = a_reg[q].y;
            As[p][aC4 + 2][aRow + q * 64] = a_reg[q].z;
            As[p][aC4 + 3][aRow + q * 64] = a_reg[q].w;
        }
        if (!TRANS_B) {
            *reinterpret_cast<float4*>(&Bs[p][bRowN][bColN]) = b_reg;
        } else {
            Bs[p][aC4 + 0][aRow] = b_reg.x;
            Bs[p][aC4 + 1][aRow] = b_reg.y;
            Bs[p][aC4 + 2][aRow] = b_reg.z;
            Bs[p][aC4 + 3][aRow] = b_reg.w;
        }
    };

    unsigned long long acc[NP][4];
#pragma unroll
    for (int pi = 0; pi < NP; pi++)
#pragma unroll
        for (int j = 0; j < 4; j++) acc[pi][j] = 0ull;

    const int niter = K / 16;
    ldg(0);
    sts(0);
    __syncthreads();

    int p = 0;
    float4 afr[2][QM];
    unsigned long long bfr[2][4];

    auto ldfrag = [&](int kk, int fb) {
#pragma unroll
        for (int q = 0; q < QM; q++)
            afr[fb][q] = *reinterpret_cast<const float4*>(&As[p][kk][q * 64 + ty * 4]);
        float4 bv = *reinterpret_cast<const float4*>(&Bs[p][kk][tx * 4]);
        bfr[fb][0] = f2pack(bv.x, bv.x);
        bfr[fb][1] = f2pack(bv.y, bv.y);
        bfr[fb][2] = f2pack(bv.z, bv.z);
        bfr[fb][3] = f2pack(bv.w, bv.w);
    };
    auto comp = [&](int fb) {
        unsigned long long ap[NP];
#pragma unroll
        for (int q = 0; q < QM; q++) {
            ap[q * 2 + 0] = f2pack(afr[fb][q].x, afr[fb][q].y);
            ap[q * 2 + 1] = f2pack(afr[fb][q].z, afr[fb][q].w);
        }
#pragma unroll
        for (int j = 0; j < 4; j++)
#pragma unroll
            for (int pi = 0; pi < NP; pi++)
                fma2(acc[pi][j], ap[pi], bfr[fb][j]);
    };

    for (int it = 0; it < niter; ++it) {
        if (it + 1 < niter) ldg((it + 1) * 16);   // global prefetch in flight
        ldfrag(0, 0);
#pragma unroll
        for (int kk = 0; kk < 16; kk++) {
            if (kk + 1 < 16) ldfrag(kk + 1, (kk + 1) & 1);  // frag pipeline
            comp(kk & 1);
        }
        if (it + 1 < niter) {
            sts(p ^ 1);
            __syncthreads();
            p ^= 1;
        }
    }

    // epilogue: acc pair pi holds rows (quad*64 + ty*4 + (pi&1)*2, +1)
#pragma unroll
    for (int pi = 0; pi < NP; pi++) {
        const int r0 = bm + (pi >> 1) * 64 + ty * 4 + (pi & 1) * 2;
        const int col = bn + tx * 4;
        float lo[4], hi[4];
#pragma unroll
        for (int j = 0; j < 4; j++) f2unpack(lo[j], hi[j], acc[pi][j]);
        float4 v0, v1;
        v0.x = lo[0] * alpha; v0.y = lo[1] * alpha; v0.z = lo[2] * alpha; v0.w = lo[3] * alpha;
        v1.x = hi[0] * alpha; v1.y = hi[1] * alpha; v1.z = hi[2] * alpha; v1.w = hi[3] * alpha;
        if (bias) {
            const float* bp = bias + col;
            v0.x += bp[0]; v0.y += bp[1]; v0.z += bp[2]; v0.w += bp[3];
            v1.x += bp[0]; v1.y += bp[1]; v1.z += bp[2]; v1.w += bp[3];
        }
        *reinterpret_cast<float4*>(C + (size_t)r0 * ldc + col) = v0;
        *reinterpret_cast<float4*>(C + (size_t)(r0 + 1) * ldc + col) = v1;
    }
}

// ---------------- K1: projections qp = query@Wq, kp = key@Wk, vp = value@Wq ----------------
__global__ void __launch_bounds__(256) k_proj(
    const float* __restrict__ q, const float* __restrict__ k,
    const float* __restrict__ v,
    const float* __restrict__ Wq, const float* __restrict__ Wk)
{
    int z = blockIdx.z;
    const float* A = (z == 0) ? q : (z == 1) ? k : v;
    const float* W = (z == 1) ? Wk : Wq;   // value uses Wq (bug preserved from source)
    float* C = (z == 0) ? g_qp : (z == 1) ? g_kp : g_vp;
    gemm3<128, false>(A, NE, W, NE, C, NE, NE, 1.0f, nullptr);
}

// ---------------- K2 (merged): wk2 (z<8), S1 (z in 8..23), bias2 (z==24) ----------------
__global__ void __launch_bounds__(256) k_mid(
    const float* __restrict__ Wr, const float* __restrict__ br)
{
    const int z = blockIdx.z;
    if (z < 8) {
        // Wk2[b,k,h,:] = (1/8) * kp_head(b,k,h,:) @ Wr[h*64:(h+1)*64, :]
        const int h = z;
        gemm3<128, false>(g_kp + h * ND, NE,
                          Wr + (size_t)h * ND * NE, NE,
                          g_wk2 + (size_t)h * NE, NH * NE,
                          ND, 0.125f, nullptr);
    } else if (z < 24) {
        // S1[b,h,q,k] = (1/8) * qp_h @ kp_h^T
        if (blockIdx.x >= 4 || blockIdx.y >= 2) return;
        const int zz = z - 8;            // b*NH + h
        const int b = zz >> 3, h = zz & 7;
        gemm3<128, true>(g_qp + (size_t)b * NL * NE + h * ND, NE,
                         g_kp + (size_t)b * NL * NE + h * ND, NE,
                         g_S1 + (size_t)zz * NL * NL, NL,
                         ND, 0.125f, nullptr);
    } else {
        // bias2[b,k,h] = (1/8) * dot(br_head, kp_head)
        const int blk = blockIdx.y * 8 + blockIdx.x;
        if (blk >= 16) return;
        const int idx = blk * 256 + threadIdx.x;   // NB*NL*NH = 4096
        const int h = idx & (NH - 1);
        const int row = idx >> 3;
        float s = 0.f;
#pragma unroll 8
        for (int e = 0; e < ND; e++)
            s += br[h * ND + e] * g_kp[(size_t)row * NE + h * ND + e];
        g_bias2[idx] = s * 0.125f;
    }
}

// ---------------- K4: relation streaming pass ----------------
__global__ void __launch_bounds__(256, 2) k_rel(const float* __restrict__ relation)
{
    const int kpos = blockIdx.x;
    const int b = blockIdx.y;
    const int tid = threadIdx.x;
    const int warp = tid >> 5;
    const int lane = tid & 31;

    __shared__ float4 wk2s4[NH * NE / 4];   // 16 KB
    __shared__ float b2s[NH];

    {
        const float4* src = reinterpret_cast<const float4*>(
            g_wk2 + (size_t)(b * NL + kpos) * NH * NE);
        for (int i = tid; i < NH * NE / 4; i += 256) wk2s4[i] = src[i];
        if (tid < NH) b2s[tid] = g_bias2[(size_t)(b * NL + kpos) * NH + tid];
    }
    __syncthreads();

    for (int pass = 0; pass < 8; pass++) {
        const int q0 = pass * 32 + warp * 4;   // this warp: q0..q0+3

        const float4* rp0 = reinterpret_cast<const float4*>(
            relation + ((size_t)(b * NL + q0 + 0) * NL + kpos) * NE);
        const float4* rp1 = reinterpret_cast<const float4*>(
            relation + ((size_t)(b * NL + q0 + 1) * NL + kpos) * NE);
        const float4* rp2 = reinterpret_cast<const float4*>(
            relation + ((size_t)(b * NL + q0 + 2) * NL + kpos) * NE);
        const float4* rp3 = reinterpret_cast<const float4*>(
            relation + ((size_t)(b * NL + q0 + 3) * NL + kpos) * NE);

        float vals[32];   // vals[qq*8 + h]
#pragma unroll
        for (int i = 0; i < 32; i++) vals[i] = 0.f;

#pragma unroll
        for (int i128 = 0; i128 < 4; i128++) {
            float4 r0 = rp0[i128 * 32 + lane];
            float4 r1 = rp1[i128 * 32 + lane];
            float4 r2 = rp2[i128 * 32 + lane];
            float4 r3 = rp3[i128 * 32 + lane];
#pragma unroll
            for (int h = 0; h < NH; h++) {
                float4 w = wk2s4[h * 128 + i128 * 32 + lane];
                vals[0 * 8 + h] += r0.x * w.x + r0.y * w.y + r0.z * w.z + r0.w * w.w;
                vals[1 * 8 + h] += r1.x * w.x + r1.y * w.y + r1.z * w.z + r1.w * w.w;
                vals[2 * 8 + h] += r2.x * w.x + r2.y * w.y + r2.z * w.z + r2.w * w.w;
                vals[3 * 8 + h] += r3.x * w.x + r3.y * w.y + r3.z * w.z + r3.w * w.w;
            }
        }

        // transpose-reduce: lane l ends with full sum of vals[l]
#pragma unroll
        for (int off = 16; off > 0; off >>= 1) {
            bool hi = (lane & off) != 0;
#pragma unroll
            for (int i = 0; i < 16; i++) {
                if (i < off) {
                    float send = hi ? vals[i] : vals[i + off];
                    float recv = __shfl_xor_sync(0xffffffffu, send, off);
                    vals[i] = (hi ? vals[i + off] : vals[i]) + recv;
                }
            }
        }

        const int qq = lane >> 3;
        const int h = lane & 7;
        const int q = q0 + qq;
        float s1 = g_S1[(((size_t)b * NH + h) * NL + q) * NL + kpos];
        g_S[(((size_t)b * NL + q) * NL + kpos) * NH + h] = vals[0] + s1 + b2s[h];
    }
}

// ---------------- K5: softmax over k + write probs ----------------
__global__ void __launch_bounds__(256) k_softmax(float* __restrict__ a_out, int write_a)
{
    const int q = blockIdx.x;
    const int b = blockIdx.y;
    const int tid = threadIdx.x;
    const int warp = tid >> 5;   // = head
    const int lane = tid & 31;

    __shared__ float Ss[NL][NH + 1];   // padded

    const float* Srow = g_S + (size_t)(b * NL + q) * NL * NH;
    for (int i = tid; i < NL * NH / 4; i += 256) {
        float4 v = reinterpret_cast<const float4*>(Srow)[i];
        int idx = i * 4;
        int kk = idx >> 3, h0 = idx & 7;
        Ss[kk][h0] = v.x; Ss[kk][h0 + 1] = v.y;
        Ss[kk][h0 + 2] = v.z; Ss[kk][h0 + 3] = v.w;
    }
    __syncthreads();

    const int h = warp;
    float x[8];
#pragma unroll
    for (int i = 0; i < 8; i++) x[i] = Ss[lane + 32 * i][h];

    float m = x[0];
#pragma unroll
    for (int i = 1; i < 8; i++) m = fmaxf(m, x[i]);
#pragma unroll
    for (int off = 16; off > 0; off >>= 1)
        m = fmaxf(m, __shfl_xor_sync(0xffffffffu, m, off));

    float e[8], s = 0.f;
#pragma unroll
    for (int i = 0; i < 8; i++) { e[i] = __expf(x[i] - m); s += e[i]; }
#pragma unroll
    for (int off = 16; off > 0; off >>= 1)
        s += __shfl_xor_sync(0xffffffffu, s, off);
    float inv = 1.0f / s;

    float* Prow = g_P + (((size_t)b * NH + h) * NL + q) * NL;
#pragma unroll
    for (int i = 0; i < 8; i++) {
        float p = e[i] * inv;
        Prow[lane + 32 * i] = p;
        Ss[lane + 32 * i][h] = p;    // own column only
    }
    __syncthreads();

    if (write_a) {
        float* arow = a_out + (size_t)(b * NL + q) * NL * NH;
        int t = tid;
        float4 v0 = make_float4(Ss[t][0], Ss[t][1], Ss[t][2], Ss[t][3]);
        float4 v1 = make_float4(Ss[t][4], Ss[t][5], Ss[t][6], Ss[t][7]);
        reinterpret_cast<float4*>(arow + t * 8)[0] = v0;
        reinterpret_cast<float4*>(arow + t * 8)[1] = v1;
    }
}

// ---------------- K6: attn = P @ vp per (b,h) ----------------
__global__ void __launch_bounds__(256) k_attn()
{
    int z = blockIdx.z;           // b*NH + h
    int b = z >> 3, h = z & 7;
    const float* A = g_P + (size_t)z * NL * NL;              // L x L
    const float* Bw = g_vp + (size_t)b * NL * NE + h * ND;   // L x 64, ldb=NE
    float* C = g_attn + (size_t)b * NL * NE + h * ND;        // ldc=NE
    gemm3<64, false>(A, NL, Bw, NE, C, NE, NL, 1.0f, nullptr);
}

// ---------------- K7: out = attn @ Wo^T + bo ----------------
__global__ void __launch_bounds__(256) k_out(
    const float* __restrict__ Wo, const float* __restrict__ bo,
    float* __restrict__ out)
{
    gemm3<64, true>(g_attn, NE, Wo, NE, out, NE, NE, 1.0f, bo);
}

// ---------------- launch ----------------
extern "C" void kernel_launch(void* const* d_in, const int* in_sizes, int n_in,
                              void* d_out, int out_size)
{
    const float* query    = (const float*)d_in[0];
    const float* key      = (const float*)d_in[1];
    const float* value    = (const float*)d_in[2];
    const float* relation = (const float*)d_in[3];
    const float* Wq       = (const float*)d_in[4];
    const float* Wk       = (const float*)d_in[5];
    // d_in[6] = Wv — unused (source bug: value projected with Wq)
    const float* Wr       = (const float*)d_in[7];
    const float* br       = (const float*)d_in[8];
    const float* Wo       = (const float*)d_in[9];
    const float* bo       = (const float*)d_in[10];

    float* out = (float*)d_out;
    const int out_elems = NB * NL * NE;            // 262144
    const int a_elems   = NB * NL * NL * NH;       // 1048576
    int write_a = (out_size >= out_elems + a_elems) ? 1 : 0;
    float* a_out = out + out_elems;

    dim3 blk(256);
    k_proj   <<<dim3(8, 4, 3),   blk>>>(query, key, value, Wq, Wk);
    k_mid    <<<dim3(8, 4, 25),  blk>>>(Wr, br);
    k_rel    <<<dim3(NL, NB),    blk>>>(relation);
    k_softmax<<<dim3(NL, NB),    blk>>>(a_out, write_a);
    k_attn   <<<dim3(1, 4, 16),  blk>>>();
    k_out    <<<dim3(8, 8, 1),   blk>>>(Wo, bo, out);
}